// round 6
// baseline (speedup 1.0000x reference)
#include <cuda_runtime.h>
#include <cuda_bf16.h>

namespace {

constexpr int Bn  = 512;
constexpr int DKn = 256;
constexpr int DVn = 256;
constexpr int Pn  = 2048;
constexpr float SCALEf = 1.0f / 16.0f;   // 1/sqrt(256)

constexpr int HALF_P = Pn / 2;           // 1024 p per CTA
constexpr int HALF_V = DVn / 2;          // 128 output rows per CTA

__device__ __forceinline__ unsigned smem_u32(const void* p) {
    return (unsigned)__cvta_generic_to_shared(p);
}
__device__ __forceinline__ unsigned mapa_peer(unsigned addr, unsigned rank) {
    unsigned r;
    asm("mapa.shared::cluster.u32 %0, %1, %2;" : "=r"(r) : "r"(addr), "r"(rank));
    return r;
}
__device__ __forceinline__ void st_cluster_f32(unsigned addr, float v) {
    asm volatile("st.shared::cluster.f32 [%0], %1;" :: "r"(addr), "f"(v) : "memory");
}
__device__ __forceinline__ unsigned cluster_rank() {
    unsigned r;
    asm("mov.u32 %0, %%cluster_ctarank;" : "=r"(r));
    return r;
}
__device__ __forceinline__ void cluster_sync() {
    asm volatile("barrier.cluster.arrive.aligned;" ::: "memory");
    asm volatile("barrier.cluster.wait.aligned;"   ::: "memory");
}

__global__ void __launch_bounds__(256, 2) __cluster_dims__(2, 1, 1)
attn_kernel(const float* __restrict__ Q,
            const float* __restrict__ K,
            const float* __restrict__ V,
            const int*   __restrict__ mask,
            float*       __restrict__ out)
{
    __shared__ float sQ[DKn];
    __shared__ float sW[Pn];      // full weight row (both halves, via DSMEM)
    __shared__ float sRed[8];
    __shared__ float sXmax;       // written by peer CTA
    __shared__ float sXsum;       // written by peer CTA

    const unsigned rank = cluster_rank();
    const unsigned peer = rank ^ 1u;
    const int b    = blockIdx.x >> 1;
    const int t    = threadIdx.x;
    const int lane = t & 31;
    const int warp = t >> 5;

    // ---- Q row into smem ----
    sQ[t] = Q[(size_t)b * DKn + t];
    __syncthreads();

    // ---- Phase 1: energies for this CTA's P-half (p = rank*1024 + 4t) ----
    const int p = (int)rank * HALF_P + 4 * t;
    const float* __restrict__ Kb = K + (size_t)b * DKn * Pn + p;

    float4 acc = make_float4(0.f, 0.f, 0.f, 0.f);

    #pragma unroll 1
    for (int d0 = 0; d0 < DKn; d0 += 16) {
        float4 kv[16];
        #pragma unroll
        for (int i = 0; i < 16; ++i)
            kv[i] = *reinterpret_cast<const float4*>(Kb + (size_t)(d0 + i) * Pn);
        #pragma unroll
        for (int i = 0; i < 16; ++i) {
            const float q = sQ[d0 + i];
            acc.x = fmaf(q, kv[i].x, acc.x);
            acc.y = fmaf(q, kv[i].y, acc.y);
            acc.z = fmaf(q, kv[i].z, acc.z);
            acc.w = fmaf(q, kv[i].w, acc.w);
        }
    }

    const int4 m = *reinterpret_cast<const int4*>(mask + (size_t)b * Pn + p);
    float e[4];
    e[0] = m.x ? acc.x * SCALEf : 0.f;
    e[1] = m.y ? acc.y * SCALEf : 0.f;
    e[2] = m.z ? acc.z * SCALEf : 0.f;
    e[3] = m.w ? acc.w * SCALEf : 0.f;

    // ---- Phase 2: cluster-wide softmax ----
    // local CTA max
    float lmax = fmaxf(fmaxf(e[0], e[1]), fmaxf(e[2], e[3]));
    float v = lmax;
    #pragma unroll
    for (int o = 16; o; o >>= 1) v = fmaxf(v, __shfl_xor_sync(0xffffffffu, v, o));
    if (lane == 0) sRed[warp] = v;
    __syncthreads();
    float cmax = sRed[0];
    #pragma unroll
    for (int i = 1; i < 8; ++i) cmax = fmaxf(cmax, sRed[i]);

    // exchange max with peer
    if (t == 0) st_cluster_f32(mapa_peer(smem_u32(&sXmax), peer), cmax);
    cluster_sync();
    const float gmax = fmaxf(cmax, sXmax);

    // exp + local sum; write un-normalized weights to BOTH CTAs' sW
    float w0 = __expf(e[0] - gmax);
    float w1 = __expf(e[1] - gmax);
    float w2 = __expf(e[2] - gmax);
    float w3 = __expf(e[3] - gmax);
    const float lsum = (w0 + w1) + (w2 + w3);

    *reinterpret_cast<float4*>(&sW[p]) = make_float4(w0, w1, w2, w3);
    {
        const unsigned pa = mapa_peer(smem_u32(&sW[p]), peer);
        st_cluster_f32(pa,      w0);
        st_cluster_f32(pa + 4,  w1);
        st_cluster_f32(pa + 8,  w2);
        st_cluster_f32(pa + 12, w3);
    }

    v = lsum;
    #pragma unroll
    for (int o = 16; o; o >>= 1) v += __shfl_xor_sync(0xffffffffu, v, o);
    if (lane == 0) sRed[warp] = v;
    __syncthreads();
    float csum = sRed[0];
    #pragma unroll
    for (int i = 1; i < 8; ++i) csum += sRed[i];

    if (t == 0) st_cluster_f32(mapa_peer(smem_u32(&sXsum), peer), csum);
    cluster_sync();   // also publishes remote sW halves
    const float inv = 1.0f / (csum + sXsum);

    // ---- Phase 3: this CTA computes output rows [rank*128, rank*128+128) over full P ----
    const float* __restrict__ Vb = V + (size_t)b * DVn * Pn;
    const int vr0 = (int)rank * HALF_V + warp * (HALF_V / 8);   // 16 rows per warp

    #pragma unroll 1
    for (int r = 0; r < HALF_V / 8; ++r) {
        const float* __restrict__ Vr = Vb + (size_t)(vr0 + r) * Pn + lane * 4;
        float4 a4 = make_float4(0.f, 0.f, 0.f, 0.f);
        #pragma unroll
        for (int i = 0; i < Pn / 128; ++i) {       // 16 float4 loads in flight
            const float4 vv = *reinterpret_cast<const float4*>(Vr + i * 128);
            const float4 ww = *reinterpret_cast<const float4*>(&sW[i * 128 + lane * 4]);
            a4.x = fmaf(ww.x, vv.x, a4.x);
            a4.y = fmaf(ww.y, vv.y, a4.y);
            a4.z = fmaf(ww.z, vv.z, a4.z);
            a4.w = fmaf(ww.w, vv.w, a4.w);
        }
        float s = (a4.x + a4.y) + (a4.z + a4.w);
        #pragma unroll
        for (int o = 16; o; o >>= 1) s += __shfl_xor_sync(0xffffffffu, s, o);
        if (lane == 0) out[(size_t)b * DVn + vr0 + r] = s * inv;
    }
}

} // namespace

extern "C" void kernel_launch(void* const* d_in, const int* in_sizes, int n_in,
                              void* d_out, int out_size)
{
    const float* Q    = (const float*)d_in[0];
    const float* K    = (const float*)d_in[1];
    const float* V    = (const float*)d_in[2];
    const int*   mask = (const int*)d_in[3];
    float*       out  = (float*)d_out;

    attn_kernel<<<Bn * 2, 256>>>(Q, K, V, mask, out);
}